// round 2
// baseline (speedup 1.0000x reference)
#include <cuda_runtime.h>
#include <cstdint>

// ---------------- problem dims ----------------
#define K_HALF 24
#define S_DIM  64
#define D_DIM  256
#define L_DIM  1024
#define B_SZ   4
#define KX     8
#define O_DIM  48                      // 2*K_HALF
#define K_G    16384                   // D_DIM * S_DIM  (k = d*64 + s)
#define K_TOT  18432                   // K_G + KX*D_DIM (k = 16384 + j*256 + d)
#define M_ROWS 4096                    // B_SZ * L_DIM
#define E_DIM  256

// ---------------- scratch (device globals; no cudaMalloc allowed) ----------------
__device__ float g_Aext[(size_t)M_ROWS * K_TOT];   // 302 MB: [m][k]  (A operand, tf32-rounded)
__device__ float g_Pt[(size_t)E_DIM * K_TOT];      //  19 MB: [e][k]  (B operand, K-major, tf32-rounded)

// ---------------- helpers ----------------
__device__ __forceinline__ uint32_t smem_u32(const void* p) {
    uint32_t a;
    asm("{ .reg .u64 t; cvta.to.shared.u64 t, %1; cvt.u32.u64 %0, t; }" : "=r"(a) : "l"(p));
    return a;
}

__device__ __forceinline__ float to_tf32(float v) {
    uint32_t u;
    asm("cvt.rna.tf32.f32 %0, %1;" : "=r"(u) : "f"(v));
    return __uint_as_float(u);
}

__device__ __forceinline__ void cp_async16(uint32_t dst, const void* src) {
    asm volatile("cp.async.cg.shared.global [%0], [%1], 16;" :: "r"(dst), "l"(src));
}
__device__ __forceinline__ void cp_commit() {
    asm volatile("cp.async.commit_group;" ::: "memory");
}

// m16n8k8 tf32 mma, D += A*B (fp32 accum in place)
__device__ __forceinline__ void mma8(float* d, const uint32_t* a, const uint32_t* b) {
    asm volatile(
        "mma.sync.aligned.m16n8k8.row.col.f32.tf32.tf32.f32 "
        "{%0,%1,%2,%3},{%4,%5,%6,%7},{%8,%9},{%0,%1,%2,%3};"
        : "+f"(d[0]), "+f"(d[1]), "+f"(d[2]), "+f"(d[3])
        : "r"(a[0]), "r"(a[1]), "r"(a[2]), "r"(a[3]), "r"(b[0]), "r"(b[1]));
}

__device__ __forceinline__ uint32_t lds32(uint32_t addr) {
    uint32_t v;
    asm volatile("ld.shared.b32 %0, [%1];" : "=r"(v) : "r"(addr));
    return v;
}

// ---------------- kernel 1: zero output ----------------
__global__ void k_zero(float* __restrict__ out, int n) {
    int i = blockIdx.x * blockDim.x + threadIdx.x;
    if (i < n) out[i] = 0.0f;
}

// ---------------- kernel 2: precompute Pt[e][k] (tf32-rounded) ----------------
// k < 16384 (d = k/64, s = k%64): Pt = Bv[s] * sum_o C[s,o] * W[o,d,e]
// k >= 16384 (j, d):              Pt = sum_o M2[o,j] * W[o,d,e]
// W[o,d,e] = o<24 ? Mp[o,d,e] : Mm[o-24,d,e]
__global__ void k_prep(const float* __restrict__ C, const float* __restrict__ Bv,
                       const float* __restrict__ M, const float* __restrict__ Mp,
                       const float* __restrict__ Mm) {
    int d  = blockIdx.x;          // 0..255
    int s  = threadIdx.x & 63;    // warp lanes span s => coalesced Pt writes
    int eg = threadIdx.x >> 6;    // 0..3

    float cs[O_DIM];
#pragma unroll
    for (int o = 0; o < O_DIM; o++) cs[o] = C[s * O_DIM + o];
    float bv = Bv[s];

    for (int e = eg * 64; e < eg * 64 + 64; e++) {
        float acc = 0.0f;
#pragma unroll
        for (int o = 0; o < O_DIM; o++) {
            float w = (o < K_HALF) ? __ldg(&Mp[((size_t)o * D_DIM + d) * D_DIM + e])
                                   : __ldg(&Mm[((size_t)(o - K_HALF) * D_DIM + d) * D_DIM + e]);
            acc = fmaf(cs[o], w, acc);
        }
        g_Pt[(size_t)e * K_TOT + d * S_DIM + s] = to_tf32(bv * acc);
    }

    if (s < KX) {
        int j = s;
        float mj[O_DIM];
#pragma unroll
        for (int o = 0; o < O_DIM; o++) mj[o] = M[o * KX + j];   // M is (48, 8, 1)
        for (int e = eg * 64; e < eg * 64 + 64; e++) {
            float acc = 0.0f;
#pragma unroll
            for (int o = 0; o < O_DIM; o++) {
                float w = (o < K_HALF) ? __ldg(&Mp[((size_t)o * D_DIM + d) * D_DIM + e])
                                       : __ldg(&Mm[((size_t)(o - K_HALF) * D_DIM + d) * D_DIM + e]);
                acc = fmaf(mj[o], w, acc);
            }
            g_Pt[(size_t)e * K_TOT + K_G + j * D_DIM + d] = to_tf32(acc);
        }
    }
}

// ---------------- kernel 3: LDS scan -> g_Aext[m][d*64+s] ----------------
// thread = (b, d, s) chain; warp spans 32 consecutive s => 128B coalesced stores
__global__ void k_scan(const float* __restrict__ x, const float* __restrict__ A) {
    int s    = threadIdx.x & 63;
    int half = threadIdx.x >> 6;
    int bd   = blockIdx.x * 2 + half;     // 0..1023
    int b    = bd >> 8;
    int d    = bd & 255;

    float a = A[s];
    float h = 0.0f;
    const float* xp = x + (size_t)b * L_DIM * D_DIM + d;
    float* op = g_Aext + (size_t)b * L_DIM * K_TOT + d * S_DIM + s;

    for (int l = 0; l < L_DIM; l++) {
        float xv = __ldg(xp + (size_t)l * D_DIM);
        h = fmaf(h, a, xv);               // g = A*g + x   (Bv folded into Pt)
        op[(size_t)l * K_TOT] = to_tf32(h);
    }
}

// ---------------- kernel 4: shift taps -> g_Aext[m][16384 + j*256 + d] ----------------
__global__ void k_shift(const float* __restrict__ x) {
    int idx = blockIdx.x * 256 + threadIdx.x;   // 4096*2048 = 8,388,608
    int m = idx >> 11;
    int r = idx & 2047;
    int j = r >> 8;
    int d = r & 255;
    int b = m >> 10;
    int l = m & 1023;
    float v = (l >= j) ? x[((size_t)b * L_DIM + (l - j)) * D_DIM + d] : 0.0f;
    g_Aext[(size_t)m * K_TOT + K_G + r] = to_tf32(v);
}

// ---------------- kernel 5: GEMM  out[m][e] += A[m][k] * Pt[e][k] ----------------
// CTA tile 128(M) x 256(N); 8 warps as 2(M) x 4(N); warp tile 64x64.
// mma.sync.m16n8k8 tf32, fp32 accumulate. 3-stage cp.async pipeline, KTILE=32.
// Smem rows are 128B (32 floats); 16B chunks XOR-swizzled by (row & 7) =>
// all fragment lds.32 patterns are 32-bank conflict-free.
#define NST   3
#define KTILE 32
#define KSPLIT 4
#define KCH   (K_TOT / KSPLIT)          // 4608
#define NSTG  (KCH / KTILE)             // 144
#define A_STG 16384                     // 128 rows * 128B
#define B_STG 32768                     // 256 rows * 128B
#define STG   (A_STG + B_STG)           // 49152
#define SMEM_DYN (NST * STG)            // 147456

__global__ void __launch_bounds__(256, 1)
k_gemm(float* __restrict__ out) {
    extern __shared__ char smem[];
    uint32_t sb = smem_u32(smem);

    int tid  = threadIdx.x;
    int lane = tid & 31;
    int wid  = tid >> 5;
    int wm   = wid >> 2;                 // 0..1
    int wn   = wid & 3;                  // 0..3
    int m0   = blockIdx.x * 128;
    int k0   = blockIdx.y * KCH;

    const float* Ab = g_Aext + (size_t)m0 * K_TOT + k0;
    const float* Bb = g_Pt + k0;

    auto copy_stage = [&](int st) {
        uint32_t base = sb + (st % NST) * STG;
        int kf = st * KTILE;
#pragma unroll
        for (int it = 0; it < 12; it++) {
            int id = tid + it * 256;                 // 0..3071 16B chunks
            if (id < 1024) {                         // A: 128 rows x 8 chunks
                int r = id >> 3, ch = id & 7;
                cp_async16(base + r * 128 + ((ch ^ (r & 7)) << 4),
                           Ab + (size_t)r * K_TOT + kf + ch * 4);
            } else {                                 // B: 256 rows x 8 chunks
                int id2 = id - 1024;
                int r = id2 >> 3, ch = id2 & 7;
                cp_async16(base + A_STG + r * 128 + ((ch ^ (r & 7)) << 4),
                           Bb + (size_t)r * K_TOT + kf + ch * 4);
            }
        }
    };

    float acc[4][8][4];
#pragma unroll
    for (int i = 0; i < 4; i++)
#pragma unroll
        for (int j = 0; j < 8; j++)
#pragma unroll
            for (int c = 0; c < 4; c++) acc[i][j][c] = 0.0f;

    copy_stage(0); cp_commit();
    copy_stage(1); cp_commit();

    int lr = lane >> 2;                  // 0..7 (row within 8-group)
    int lc = lane & 3;                   // 0..3 (col within 4-group)

    for (int ks = 0; ks < NSTG; ks++) {
        asm volatile("cp.async.wait_group 1;" ::: "memory");
        __syncthreads();
        if (ks + 2 < NSTG) copy_stage(ks + 2);       // buffer (ks-1)%3, freed by the barrier
        cp_commit();

        uint32_t aBase = sb + (ks % NST) * STG;
        uint32_t bBase = aBase + A_STG;

#pragma unroll
        for (int kk = 0; kk < 4; kk++) {             // 4 x k8 steps
            int c0 = kk * 8 + lc;
            int c1 = c0 + 4;
            int p0 = (c0 >> 2);                      // = 2*kk
            int p1 = (c1 >> 2);                      // = 2*kk+1
            int b0 = (c0 & 3) << 2;                  // byte within chunk
            int b1 = (c1 & 3) << 2;

            uint32_t bf[8][2];
#pragma unroll
            for (int nf = 0; nf < 8; nf++) {
                int er = wn * 64 + nf * 8 + lr;
                uint32_t rowb = bBase + er * 128;
                int sw = er & 7;
                bf[nf][0] = lds32(rowb + ((p0 ^ sw) << 4) + b0);
                bf[nf][1] = lds32(rowb + ((p1 ^ sw) << 4) + b1);
            }
#pragma unroll
            for (int mf = 0; mf < 4; mf++) {
                int r0 = wm * 64 + mf * 16 + lr;
                int r1 = r0 + 8;
                uint32_t row0 = aBase + r0 * 128;
                uint32_t row1 = aBase + r1 * 128;
                int s0 = r0 & 7;                     // == r1 & 7
                uint32_t af[4];
                af[0] = lds32(row0 + ((p0 ^ s0) << 4) + b0);   // (r0, c0)
                af[1] = lds32(row1 + ((p0 ^ s0) << 4) + b0);   // (r1, c0)
                af[2] = lds32(row0 + ((p1 ^ s0) << 4) + b1);   // (r0, c1)
                af[3] = lds32(row1 + ((p1 ^ s0) << 4) + b1);   // (r1, c1)
#pragma unroll
                for (int nf = 0; nf < 8; nf++)
                    mma8(acc[mf][nf], af, bf[nf]);
            }
        }
    }

    // epilogue: split-K reduce via atomicAdd (out pre-zeroed)
#pragma unroll
    for (int mf = 0; mf < 4; mf++) {
#pragma unroll
        for (int nf = 0; nf < 8; nf++) {
            int r = m0 + wm * 64 + mf * 16 + lr;
            int c = wn * 64 + nf * 8 + (lc << 1);
            atomicAdd(&out[(size_t)r * E_DIM + c],       acc[mf][nf][0]);
            atomicAdd(&out[(size_t)r * E_DIM + c + 1],   acc[mf][nf][1]);
            atomicAdd(&out[(size_t)(r + 8) * E_DIM + c],     acc[mf][nf][2]);
            atomicAdd(&out[(size_t)(r + 8) * E_DIM + c + 1], acc[mf][nf][3]);
        }
    }
}

// ---------------- launch ----------------
extern "C" void kernel_launch(void* const* d_in, const int* in_sizes, int n_in,
                              void* d_out, int out_size) {
    const float* x  = (const float*)d_in[0];
    const float* A  = (const float*)d_in[1];
    const float* Bv = (const float*)d_in[2];
    const float* C  = (const float*)d_in[3];
    const float* M  = (const float*)d_in[4];
    const float* Mp = (const float*)d_in[5];
    const float* Mm = (const float*)d_in[6];
    float* out = (float*)d_out;

    static bool attr_set = false;
    if (!attr_set) {
        cudaFuncSetAttribute(k_gemm, cudaFuncAttributeMaxDynamicSharedMemorySize, SMEM_DYN);
        attr_set = true;
    }

    k_zero<<<(out_size + 255) / 256, 256>>>(out, out_size);
    k_prep<<<D_DIM, 256>>>(C, Bv, M, Mp, Mm);
    k_scan<<<512, 128>>>(x, A);
    k_shift<<<(M_ROWS * (KX * D_DIM)) / 256, 256>>>(x);

    dim3 grid(M_ROWS / 128, KSPLIT);
    k_gemm<<<grid, 256, SMEM_DYN>>>(out);
}

// round 3
// speedup vs baseline: 1.0292x; 1.0292x over previous
#include <cuda_runtime.h>
#include <cstdint>

// ---------------- problem dims ----------------
#define K_HALF 24
#define S_DIM  64
#define D_DIM  256
#define L_DIM  1024
#define B_SZ   4
#define KX     8
#define O_DIM  48                      // 2*K_HALF
#define K_G    16384                   // D_DIM * S_DIM  (k = d*64 + s)
#define K_TOT  18432                   // K_G + KX*D_DIM (k = 16384 + j*256 + d)
#define M_ROWS 4096                    // B_SZ * L_DIM
#define E_DIM  256

// ---------------- scratch (device globals; no cudaMalloc allowed) ----------------
__device__ float g_Aext[(size_t)M_ROWS * K_TOT];   // 302 MB: [m][k]  (A operand, tf32-rounded)
__device__ float g_Pt[(size_t)E_DIM * K_TOT];      //  19 MB: [e][k]  (B operand, K-major, tf32-rounded)

// ---------------- helpers ----------------
__device__ __forceinline__ uint32_t smem_u32(const void* p) {
    uint32_t a;
    asm("{ .reg .u64 t; cvta.to.shared.u64 t, %1; cvt.u32.u64 %0, t; }" : "=r"(a) : "l"(p));
    return a;
}

__device__ __forceinline__ float to_tf32(float v) {
    uint32_t u;
    asm("cvt.rna.tf32.f32 %0, %1;" : "=r"(u) : "f"(v));
    return __uint_as_float(u);
}

__device__ __forceinline__ void cp_async16(uint32_t dst, const void* src) {
    asm volatile("cp.async.cg.shared.global [%0], [%1], 16;" :: "r"(dst), "l"(src));
}
__device__ __forceinline__ void cp_commit() {
    asm volatile("cp.async.commit_group;" ::: "memory");
}

// m16n8k8 tf32 mma, D += A*B (fp32 accum in place)
__device__ __forceinline__ void mma8(float* d, const uint32_t* a, const uint32_t* b) {
    asm volatile(
        "mma.sync.aligned.m16n8k8.row.col.f32.tf32.tf32.f32 "
        "{%0,%1,%2,%3},{%4,%5,%6,%7},{%8,%9},{%0,%1,%2,%3};"
        : "+f"(d[0]), "+f"(d[1]), "+f"(d[2]), "+f"(d[3])
        : "r"(a[0]), "r"(a[1]), "r"(a[2]), "r"(a[3]), "r"(b[0]), "r"(b[1]));
}

// ldmatrix x4: four 8x8 b16 matrices (= four 8x4 f32 tiles). Lane l supplies the
// row address for matrix l/8, row l%8. Result: lane l gets (row l/4, f32-word l%4).
__device__ __forceinline__ void ldsm4(uint32_t* r, uint32_t addr) {
    asm volatile("ldmatrix.sync.aligned.m8n8.x4.shared.b16 {%0,%1,%2,%3}, [%4];"
        : "=r"(r[0]), "=r"(r[1]), "=r"(r[2]), "=r"(r[3]) : "r"(addr));
}

// ---------------- kernel 1: zero output ----------------
__global__ void k_zero(float* __restrict__ out, int n) {
    int i = blockIdx.x * blockDim.x + threadIdx.x;
    if (i < n) out[i] = 0.0f;
}

// ---------------- kernel 2: precompute Pt[e][k] (tf32-rounded) ----------------
__global__ void k_prep(const float* __restrict__ C, const float* __restrict__ Bv,
                       const float* __restrict__ M, const float* __restrict__ Mp,
                       const float* __restrict__ Mm) {
    int d  = blockIdx.x;          // 0..255
    int s  = threadIdx.x & 63;    // warp lanes span s => coalesced Pt writes
    int eg = threadIdx.x >> 6;    // 0..3

    float cs[O_DIM];
#pragma unroll
    for (int o = 0; o < O_DIM; o++) cs[o] = C[s * O_DIM + o];
    float bv = Bv[s];

    for (int e = eg * 64; e < eg * 64 + 64; e++) {
        float acc = 0.0f;
#pragma unroll
        for (int o = 0; o < O_DIM; o++) {
            float w = (o < K_HALF) ? __ldg(&Mp[((size_t)o * D_DIM + d) * D_DIM + e])
                                   : __ldg(&Mm[((size_t)(o - K_HALF) * D_DIM + d) * D_DIM + e]);
            acc = fmaf(cs[o], w, acc);
        }
        g_Pt[(size_t)e * K_TOT + d * S_DIM + s] = to_tf32(bv * acc);
    }

    if (s < KX) {
        int j = s;
        float mj[O_DIM];
#pragma unroll
        for (int o = 0; o < O_DIM; o++) mj[o] = M[o * KX + j];   // M is (48, 8, 1)
        for (int e = eg * 64; e < eg * 64 + 64; e++) {
            float acc = 0.0f;
#pragma unroll
            for (int o = 0; o < O_DIM; o++) {
                float w = (o < K_HALF) ? __ldg(&Mp[((size_t)o * D_DIM + d) * D_DIM + e])
                                       : __ldg(&Mm[((size_t)(o - K_HALF) * D_DIM + d) * D_DIM + e]);
                acc = fmaf(mj[o], w, acc);
            }
            g_Pt[(size_t)e * K_TOT + K_G + j * D_DIM + d] = to_tf32(acc);
        }
    }
}

// ---------------- kernel 3: LDS scan -> g_Aext[m][d*64+s] ----------------
__global__ void k_scan(const float* __restrict__ x, const float* __restrict__ A) {
    int s    = threadIdx.x & 63;
    int half = threadIdx.x >> 6;
    int bd   = blockIdx.x * 2 + half;     // 0..1023
    int b    = bd >> 8;
    int d    = bd & 255;

    float a = A[s];
    float h = 0.0f;
    const float* xp = x + (size_t)b * L_DIM * D_DIM + d;
    float* op = g_Aext + (size_t)b * L_DIM * K_TOT + d * S_DIM + s;

#pragma unroll 1
    for (int l = 0; l < L_DIM; l += 4) {
        float x0 = __ldg(xp + (size_t)l * D_DIM);
        float x1 = __ldg(xp + (size_t)(l + 1) * D_DIM);
        float x2 = __ldg(xp + (size_t)(l + 2) * D_DIM);
        float x3 = __ldg(xp + (size_t)(l + 3) * D_DIM);
        h = fmaf(h, a, x0); op[(size_t)l * K_TOT]       = to_tf32(h);
        h = fmaf(h, a, x1); op[(size_t)(l + 1) * K_TOT] = to_tf32(h);
        h = fmaf(h, a, x2); op[(size_t)(l + 2) * K_TOT] = to_tf32(h);
        h = fmaf(h, a, x3); op[(size_t)(l + 3) * K_TOT] = to_tf32(h);
    }
}

// ---------------- kernel 4: shift taps (float4) ----------------
// element block = (m, j, d4): out[m][K_G + j*256 + d4*4 ..+3]
__global__ void k_shift(const float* __restrict__ x) {
    int idx = blockIdx.x * 256 + threadIdx.x;   // 4096*8*64 = 2,097,152
    int m  = idx >> 9;
    int r  = idx & 511;
    int j  = r >> 6;
    int d4 = r & 63;
    int b  = m >> 10;
    int l  = m & 1023;
    float4 v = make_float4(0.f, 0.f, 0.f, 0.f);
    if (l >= j)
        v = *(const float4*)(x + ((size_t)b * L_DIM + (l - j)) * D_DIM + d4 * 4);
    v.x = to_tf32(v.x); v.y = to_tf32(v.y); v.z = to_tf32(v.z); v.w = to_tf32(v.w);
    *(float4*)(g_Aext + (size_t)m * K_TOT + K_G + j * D_DIM + d4 * 4) = v;
}

// ---------------- kernel 5: GEMM  out[m][e] += A[m][k] * Pt[e][k] ----------------
// CTA tile 128(M) x 256(N); 8 warps as 2(M) x 4(N); warp tile 64x64.
// mma.sync.m16n8k8 tf32. 3-stage cp.async pipeline, KTILE=32.
// Smem rows 128B; 16B chunks XOR-swizzled by (row&7); fragments via ldmatrix.x4.
#define NST   3
#define KTILE 32
#define KSPLIT 4
#define KCH   (K_TOT / KSPLIT)          // 4608
#define NSTG  (KCH / KTILE)             // 144
#define A_STG 16384                     // 128 rows * 128B
#define B_STG 32768                     // 256 rows * 128B
#define STG   (A_STG + B_STG)           // 49152
#define SMEM_DYN (NST * STG)            // 147456

__global__ void __launch_bounds__(256, 1)
k_gemm(float* __restrict__ out) {
    extern __shared__ char smem[];
    uint32_t sb = smem_u32(smem);

    int tid  = threadIdx.x;
    int lane = tid & 31;
    int wid  = tid >> 5;
    int wm   = wid >> 2;                 // 0..1
    int wn   = wid & 3;                  // 0..3
    int m0   = blockIdx.x * 128;
    int k0   = blockIdx.y * KCH;

    const float* Ab = g_Aext + (size_t)m0 * K_TOT + k0;
    const float* Bb = g_Pt + k0;

    auto copy_stage = [&](int st) {
        uint32_t base = sb + (st % NST) * STG;
        int kf = st * KTILE;
#pragma unroll
        for (int it = 0; it < 12; it++) {
            int id = tid + it * 256;                 // 0..3071 16B chunks
            if (id < 1024) {                         // A: 128 rows x 8 chunks
                int r = id >> 3, ch = id & 7;
                cp_async16(base + r * 128 + ((ch ^ (r & 7)) << 4),
                           Ab + (size_t)r * K_TOT + kf + ch * 4);
            } else {                                 // B: 256 rows x 8 chunks
                int id2 = id - 1024;
                int r = id2 >> 3, ch = id2 & 7;
                cp_async16(base + A_STG + r * 128 + ((ch ^ (r & 7)) << 4),
                           Bb + (size_t)r * K_TOT + kf + ch * 4);
            }
        }
    };

    float acc[4][8][4];
#pragma unroll
    for (int i = 0; i < 4; i++)
#pragma unroll
        for (int j = 0; j < 8; j++)
#pragma unroll
            for (int c = 0; c < 4; c++) acc[i][j][c] = 0.0f;

    copy_stage(0); cp_commit();
    copy_stage(1); cp_commit();

    // ldmatrix per-lane address components (see derivation in comments):
    // A matrices for (kk,mf): m&1 -> +8 rows, m>>1 -> +1 chunk
    //   lane row  = (lane&7) + 8*((lane>>3)&1);  lane chunk bit = lane>>4
    // B matrices for (kk,nfp): m&1 -> +1 chunk, m>>1 -> +8 rows (next nf)
    //   lane row  = (lane&7) + 8*(lane>>4);      lane chunk bit = (lane>>3)&1
    int sw   = lane & 7;
    int aRow = (lane & 7) + (((lane >> 3) & 1) << 3);
    int aCb  = lane >> 4;
    int bRow = (lane & 7) + ((lane >> 4) << 3);
    int bCb  = (lane >> 3) & 1;

    int lr = lane >> 2;                  // epilogue row within 8-group
    int lc = lane & 3;

    for (int ks = 0; ks < NSTG; ks++) {
        asm volatile("cp.async.wait_group 1;" ::: "memory");
        __syncthreads();
        if (ks + 2 < NSTG) copy_stage(ks + 2);       // buffer (ks-1)%3, freed by the barrier
        cp_commit();

        uint32_t aBase = sb + (ks % NST) * STG;
        uint32_t bBase = aBase + A_STG;
        uint32_t aLane = aBase + (wm * 64 + aRow) * 128;
        uint32_t bLane = bBase + (wn * 64 + bRow) * 128;

#pragma unroll
        for (int kk = 0; kk < 4; kk++) {             // 4 x k8 steps
            uint32_t breg[16];                       // [nfp]{nf0.b0, nf0.b1, nf1.b0, nf1.b1}
#pragma unroll
            for (int nfp = 0; nfp < 4; nfp++)
                ldsm4(&breg[nfp * 4],
                      bLane + nfp * 16 * 128 + (((2 * kk + bCb) ^ sw) << 4));
#pragma unroll
            for (int mf = 0; mf < 4; mf++) {
                uint32_t areg[4];
                ldsm4(areg, aLane + mf * 16 * 128 + (((2 * kk + aCb) ^ sw) << 4));
#pragma unroll
                for (int nf = 0; nf < 8; nf++)
                    mma8(acc[mf][nf], areg, &breg[(nf >> 1) * 4 + (nf & 1) * 2]);
            }
        }
    }

    // epilogue: split-K reduce via atomicAdd (out pre-zeroed)
#pragma unroll
    for (int mf = 0; mf < 4; mf++) {
#pragma unroll
        for (int nf = 0; nf < 8; nf++) {
            int r = m0 + wm * 64 + mf * 16 + lr;
            int c = wn * 64 + nf * 8 + (lc << 1);
            atomicAdd(&out[(size_t)r * E_DIM + c],           acc[mf][nf][0]);
            atomicAdd(&out[(size_t)r * E_DIM + c + 1],       acc[mf][nf][1]);
            atomicAdd(&out[(size_t)(r + 8) * E_DIM + c],     acc[mf][nf][2]);
            atomicAdd(&out[(size_t)(r + 8) * E_DIM + c + 1], acc[mf][nf][3]);
        }
    }
}

// ---------------- launch ----------------
extern "C" void kernel_launch(void* const* d_in, const int* in_sizes, int n_in,
                              void* d_out, int out_size) {
    const float* x  = (const float*)d_in[0];
    const float* A  = (const float*)d_in[1];
    const float* Bv = (const float*)d_in[2];
    const float* C  = (const float*)d_in[3];
    const float* M  = (const float*)d_in[4];
    const float* Mp = (const float*)d_in[5];
    const float* Mm = (const float*)d_in[6];
    float* out = (float*)d_out;

    static bool attr_set = false;
    if (!attr_set) {
        cudaFuncSetAttribute(k_gemm, cudaFuncAttributeMaxDynamicSharedMemorySize, SMEM_DYN);
        attr_set = true;
    }

    k_zero<<<(out_size + 255) / 256, 256>>>(out, out_size);
    k_prep<<<D_DIM, 256>>>(C, Bv, M, Mp, Mm);
    k_scan<<<512, 128>>>(x, A);
    k_shift<<<(M_ROWS * KX * 64) / 256, 256>>>(x);

    dim3 grid(M_ROWS / 128, KSPLIT);
    k_gemm<<<grid, 256, SMEM_DYN>>>(out);
}